// round 13
// baseline (speedup 1.0000x reference)
#include <cuda_runtime.h>
#include <cuda_fp16.h>

// Problem constants (fixed by the reference setup)
#define B_ 4
#define C_ 3
#define H_ 512
#define W_ 960
#define HW_ (H_ * W_)

// Tile geometry: 64x16 pixels per block, 256 threads, 4 pixels/thread (along y)
#define TW 64
#define TH 16
#define NTHREADS 256
#define SWU (TW + 13)         // 77 used cols: halo 6 left, 7 right
#define PITCH 80              // row pitch in texels; 80 % 16 == 0 -> bank hash dy-invariant
#define SH (TH + 13)          // 29 rows: halo 6 top, 7 bottom
#define NTEX (SWU * SH)       // texels to stage

__global__ void __launch_bounds__(NTHREADS, 4)
fi_tiled_h13_kernel(const float* __restrict__ inp,
                    const float* __restrict__ flow,
                    const float* __restrict__ filt,
                    float* __restrict__ out)
{
    // one 8-byte texel per pixel: (half c0, half c1, half c2, 0)
    __shared__ uint2 sm[PITCH * SH];   // 18.6 KB

    const int x0 = blockIdx.x * TW;
    const int y0 = blockIdx.y * TH;
    const int b  = blockIdx.z;
    const int tid = threadIdx.x;

    const float* __restrict__ ibase = inp + (size_t)b * C_ * HW_;

    // ---- stage tile + halo into smem (border clamp baked in, fp32 -> fp16x3) ----
    #pragma unroll 3
    for (int idx = tid; idx < NTEX; idx += NTHREADS) {
        const int j = idx / SWU;
        const int i = idx - j * SWU;
        const int gy = min(max(y0 - 6 + j, 0), H_ - 1);
        const int gx = min(max(x0 - 6 + i, 0), W_ - 1);
        const int g  = gy * W_ + gx;
        const float v0 = ibase[g];
        const float v1 = ibase[g + HW_];
        const float v2 = ibase[g + 2 * HW_];
        __half2 h01 = __floats2half2_rn(v0, v1);
        __half2 h2p = __floats2half2_rn(v2, 0.0f);
        uint2 u;
        u.x = *reinterpret_cast<unsigned*>(&h01);
        u.y = *reinterpret_cast<unsigned*>(&h2p);
        sm[j * PITCH + i] = u;
    }
    __syncthreads();

    const int x     = x0 + (tid & 63);
    const int tyg   = tid >> 6;            // 0..3
    const int ybase = y0 + tyg * 4;

    const float* __restrict__ flowx = flow + ((size_t)b * 2 + 0) * HW_;
    const float* __restrict__ flowy = flow + ((size_t)b * 2 + 1) * HW_;
    const float* __restrict__ fbb   = filt + (size_t)b * 16 * HW_;
    float* __restrict__ obb         = out  + (size_t)b * C_ * HW_;

    // ---- hoist ALL flow loads: 8 independent LDGs in flight up-front ----
    float fxv[4], fyv[4];
    #pragma unroll
    for (int k = 0; k < 4; k++) {
        fxv[k] = __ldcs(flowx + (ybase + k) * W_ + x);
        fyv[k] = __ldcs(flowy + (ybase + k) * W_ + x);
    }

    // ---- prime filter pipeline: k=0's 16 taps ----
    float fcur[16];
    {
        const float* fb = fbb + ybase * W_ + x;
        #pragma unroll
        for (int t = 0; t < 16; t++) fcur[t] = __ldcs(fb + t * HW_);
    }

    #pragma unroll
    for (int k = 0; k < 4; k++) {
        const int y   = ybase + k;
        const int pix = y * W_ + x;

        // ---- issue k+1's filter loads FIRST (hidden behind this body) ----
        float fnxt[16];
        if (k < 3) {
            const float* fb = fbb + pix + W_;
            #pragma unroll
            for (int t = 0; t < 16; t++) fnxt[t] = __ldcs(fb + t * HW_);
        }

        const float cfx = fxv[k], cfy = fyv[k];
        const float x2 = (float)x + cfx;
        const float y2 = (float)y + cfy;

        const bool valid =
            (x2 >= 0.0f) && (x2 <= (float)(W_ - 1)) &&
            (y2 >= 0.0f) && (y2 <= (float)(H_ - 1)) &&
            (fabsf(cfx) < (float)W_ * 0.5f) &&
            (fabsf(cfy) < (float)H_ * 0.5f);
        const float validf = valid ? 1.0f : 0.0f;

        const int   ix = __float2int_rd(x2);
        const int   iy = __float2int_rd(y2);
        const float a  = x2 - (float)ix;
        const float bt = y2 - (float)iy;

        const float wTL = (1.0f - a) * (1.0f - bt);
        const float wTR = a * (1.0f - bt);
        const float wBL = (1.0f - a) * bt;
        const float wBR = a * bt;

        // ---- window coords, clamped into the staged halo (branchless) ----
        const int ly  = iy - y0 + 5;
        const int lx  = ix - x0 + 5;
        const int lyc = min(max(ly, 0), SH - 5);
        const int lxc = min(max(lx, 0), SWU - 5);
        const bool fixup = valid && ((lyc != ly) || (lxc != lx));

        float r0 = 0.0f, r1 = 0.0f, r2 = 0.0f;

        // ---- fast path: 25 taps, software-pipelined by row (r12 win) ----
        {
            const uint2* s0 = sm + lyc * PITCH + lxc;

            uint2 cur[5], nxt[5];
            #pragma unroll
            for (int c = 0; c < 5; c++) cur[c] = s0[c];

            #pragma unroll
            for (int r = 0; r < 5; r++) {
                if (r < 4) {
                    const uint2* sr = s0 + (r + 1) * PITCH;
                    #pragma unroll
                    for (int c = 0; c < 5; c++) nxt[c] = sr[c];
                }

                __half2 acc01 = __floats2half2_rn(0.0f, 0.0f);
                __half2 acc2p = acc01;
                #pragma unroll
                for (int c = 0; c < 5; c++) {
                    float w = 0.0f;
                    if (r < 4 && c < 4)  w += wTL * fcur[r * 4 + c];
                    if (r < 4 && c >= 1) w += wTR * fcur[r * 4 + c - 1];
                    if (r >= 1 && c < 4) w += wBL * fcur[(r - 1) * 4 + c];
                    if (r >= 1 && c >= 1)w += wBR * fcur[(r - 1) * 4 + c - 1];

                    const uint2 u = cur[c];
                    const __half2 h01 = *reinterpret_cast<const __half2*>(&u.x);
                    const __half2 h2p = *reinterpret_cast<const __half2*>(&u.y);
                    const __half2 w2  = __float2half2_rn(w);
                    acc01 = __hfma2(w2, h01, acc01);
                    acc2p = __hfma2(w2, h2p, acc2p);
                }
                const float2 p01 = __half22float2(acc01);
                r0 += p01.x;
                r1 += p01.y;
                r2 += __low2float(acc2p);

                if (r < 4) {
                    #pragma unroll
                    for (int c = 0; c < 5; c++) cur[c] = nxt[c];
                }
            }
        }

        // ---- rare fix-up (warp-uniformly skipped ~always): global gathers ----
        if (__any_sync(0xffffffffu, fixup)) {
            if (fixup) {
                r0 = 0.0f; r1 = 0.0f; r2 = 0.0f;
                #pragma unroll 1
                for (int r = 0; r < 5; r++) {
                    const int yy = min(max(iy - 1 + r, 0), H_ - 1);
                    const float* g0 = ibase + yy * W_;
                    #pragma unroll 1
                    for (int c = 0; c < 5; c++) {
                        float w = 0.0f;
                        if (r < 4 && c < 4)  w += wTL * fcur[r * 4 + c];
                        if (r < 4 && c >= 1) w += wTR * fcur[r * 4 + c - 1];
                        if (r >= 1 && c < 4) w += wBL * fcur[(r - 1) * 4 + c];
                        if (r >= 1 && c >= 1)w += wBR * fcur[(r - 1) * 4 + c - 1];

                        const int xo = min(max(ix - 1 + c, 0), W_ - 1);
                        r0 += w * __ldg(g0 + xo);
                        r1 += w * __ldg(g0 + xo + HW_);
                        r2 += w * __ldg(g0 + xo + 2 * HW_);
                    }
                }
            }
        }

        float* ob = obb + pix;
        ob[0]       = r0 * validf;
        ob[HW_]     = r1 * validf;
        ob[2 * HW_] = r2 * validf;

        // ---- rotate filter double-buffer ----
        if (k < 3) {
            #pragma unroll
            for (int t = 0; t < 16; t++) fcur[t] = fnxt[t];
        }
    }
}

extern "C" void kernel_launch(void* const* d_in, const int* in_sizes, int n_in,
                              void* d_out, int out_size)
{
    const float* teninput  = (const float*)d_in[0];
    const float* tenflow   = (const float*)d_in[1];
    const float* tenfilter = (const float*)d_in[2];
    float* out = (float*)d_out;

    dim3 grid(W_ / TW, H_ / TH, B_);   // 15 x 32 x 4
    fi_tiled_h13_kernel<<<grid, NTHREADS>>>(teninput, tenflow, tenfilter, out);
}

// round 14
// speedup vs baseline: 1.0510x; 1.0510x over previous
#include <cuda_runtime.h>
#include <cuda_fp16.h>

// Problem constants (fixed by the reference setup)
#define B_ 4
#define C_ 3
#define H_ 512
#define W_ 960
#define HW_ (H_ * W_)

// Tile geometry: 64x16 pixels per block, 256 threads, 4 pixels/thread (along y)
#define TW 64
#define TH 16
#define NTHREADS 256
#define SWU (TW + 13)         // 77 used cols: halo 6 left, 7 right
#define PU 96                 // plane pitch in 4B words; 96 % 32 == 0 -> bank hash dy-invariant
#define SH (TH + 13)          // 29 rows: halo 6 top, 7 bottom
#define NTEX (SWU * SH)       // texels to stage
#define PLANE (PU * SH)       // words per plane

__global__ void __launch_bounds__(NTHREADS, 5)
fi_tiled_h14_kernel(const float* __restrict__ inp,
                    const float* __restrict__ flow,
                    const float* __restrict__ filt,
                    float* __restrict__ out)
{
    // Plane A: (half c0, half c1) per texel.  Plane B: (half c2[x], half c2[x+1]).
    __shared__ unsigned smA[PLANE];   // 11.1 KB
    __shared__ unsigned smB[PLANE];   // 11.1 KB

    const int x0 = blockIdx.x * TW;
    const int y0 = blockIdx.y * TH;
    const int b  = blockIdx.z;
    const int tid = threadIdx.x;

    const float* __restrict__ ibase = inp + (size_t)b * C_ * HW_;

    // ---- stage tile + halo (border clamp baked in, fp32 -> fp16) ----
    #pragma unroll 3
    for (int idx = tid; idx < NTEX; idx += NTHREADS) {
        const int j = idx / SWU;
        const int i = idx - j * SWU;
        const int gy  = min(max(y0 - 6 + j, 0), H_ - 1);
        const int gx  = min(max(x0 - 6 + i, 0), W_ - 1);
        const int gx1 = min(max(x0 - 5 + i, 0), W_ - 1);   // clamp of (unclamped gx)+1
        const int rowg = gy * W_;
        const float v0  = ibase[rowg + gx];
        const float v1  = ibase[rowg + gx + HW_];
        const float v2  = ibase[rowg + gx + 2 * HW_];
        const float v2n = ibase[rowg + gx1 + 2 * HW_];
        const __half2 a  = __floats2half2_rn(v0, v1);
        const __half2 bb = __floats2half2_rn(v2, v2n);
        smA[j * PU + i] = *reinterpret_cast<const unsigned*>(&a);
        smB[j * PU + i] = *reinterpret_cast<const unsigned*>(&bb);
    }
    __syncthreads();

    const int x     = x0 + (tid & 63);
    const int tyg   = tid >> 6;            // 0..3
    const int ybase = y0 + tyg * 4;

    const float* __restrict__ flowx = flow + ((size_t)b * 2 + 0) * HW_;
    const float* __restrict__ flowy = flow + ((size_t)b * 2 + 1) * HW_;
    const float* __restrict__ fbb   = filt + (size_t)b * 16 * HW_;
    float* __restrict__ obb         = out  + (size_t)b * C_ * HW_;

    // ---- hoist ALL flow loads ----
    float fxv[4], fyv[4];
    #pragma unroll
    for (int k = 0; k < 4; k++) {
        fxv[k] = __ldcs(flowx + (ybase + k) * W_ + x);
        fyv[k] = __ldcs(flowy + (ybase + k) * W_ + x);
    }

    #pragma unroll
    for (int k = 0; k < 4; k++) {
        const int y   = ybase + k;
        const int pix = y * W_ + x;

        const float cfx = fxv[k], cfy = fyv[k];
        const float x2 = (float)x + cfx;
        const float y2 = (float)y + cfy;

        const bool valid =
            (x2 >= 0.0f) && (x2 <= (float)(W_ - 1)) &&
            (y2 >= 0.0f) && (y2 <= (float)(H_ - 1)) &&
            (fabsf(cfx) < (float)W_ * 0.5f) &&
            (fabsf(cfy) < (float)H_ * 0.5f);
        const float validf = valid ? 1.0f : 0.0f;

        const int   ix = __float2int_rd(x2);
        const int   iy = __float2int_rd(y2);
        const float a  = x2 - (float)ix;
        const float bt = y2 - (float)iy;

        const float wTL = (1.0f - a) * (1.0f - bt);
        const float wTR = a * (1.0f - bt);
        const float wBL = (1.0f - a) * bt;
        const float wBR = a * bt;

        // ---- preload 16 filter taps ----
        float f[16];
        const float* fb = fbb + pix;
        #pragma unroll
        for (int t = 0; t < 16; t++) f[t] = __ldcs(fb + t * HW_);

        // ---- window coords, clamped into the staged halo (branchless) ----
        const int ly  = iy - y0 + 5;
        const int lx  = ix - x0 + 5;
        const int lyc = min(max(ly, 0), SH - 5);
        const int lxc = min(max(lx, 0), SWU - 5);
        const bool fixup = valid && ((lyc != ly) || (lxc != lx));

        float r0 = 0.0f, r1 = 0.0f, r2 = 0.0f;

        // ---- fast path: 25 taps, row-pipelined; A: 5 LDS.32, B: 3 LDS.32 ----
        {
            const int base = lyc * PU + lxc;

            unsigned curA[5], nxtA[5];
            unsigned curB[3], nxtB[3];
            #pragma unroll
            for (int c = 0; c < 5; c++) curA[c] = smA[base + c];
            #pragma unroll
            for (int p = 0; p < 3; p++) curB[p] = smB[base + 2 * p];

            #pragma unroll
            for (int r = 0; r < 5; r++) {
                if (r < 4) {
                    const int nb = base + (r + 1) * PU;
                    #pragma unroll
                    for (int c = 0; c < 5; c++) nxtA[c] = smA[nb + c];
                    #pragma unroll
                    for (int p = 0; p < 3; p++) nxtB[p] = smB[nb + 2 * p];
                }

                // per-row weights (fp32)
                float w[5];
                #pragma unroll
                for (int c = 0; c < 5; c++) {
                    float ww = 0.0f;
                    if (r < 4 && c < 4)  ww += wTL * f[r * 4 + c];
                    if (r < 4 && c >= 1) ww += wTR * f[r * 4 + c - 1];
                    if (r >= 1 && c < 4) ww += wBL * f[(r - 1) * 4 + c];
                    if (r >= 1 && c >= 1)ww += wBR * f[(r - 1) * 4 + c - 1];
                    w[c] = ww;
                }

                // channels 0,1: splat weight, HFMA2 against (c0,c1) texel
                __half2 acc01 = __floats2half2_rn(0.0f, 0.0f);
                #pragma unroll
                for (int c = 0; c < 5; c++) {
                    const __half2 tex = *reinterpret_cast<const __half2*>(&curA[c]);
                    acc01 = __hfma2(__float2half2_rn(w[c]), tex, acc01);
                }

                // channel 2: paired taps, weight pairs (w0,w1)(w2,w3)(w4,0)
                __half2 accB = __floats2half2_rn(0.0f, 0.0f);
                {
                    const __half2 wp0 = __floats2half2_rn(w[0], w[1]);
                    const __half2 wp1 = __floats2half2_rn(w[2], w[3]);
                    const __half2 wp2 = __floats2half2_rn(w[4], 0.0f);
                    accB = __hfma2(wp0, *reinterpret_cast<const __half2*>(&curB[0]), accB);
                    accB = __hfma2(wp1, *reinterpret_cast<const __half2*>(&curB[1]), accB);
                    accB = __hfma2(wp2, *reinterpret_cast<const __half2*>(&curB[2]), accB);
                }

                const float2 p01 = __half22float2(acc01);
                const float2 pb  = __half22float2(accB);
                r0 += p01.x;
                r1 += p01.y;
                r2 += pb.x + pb.y;

                if (r < 4) {
                    #pragma unroll
                    for (int c = 0; c < 5; c++) curA[c] = nxtA[c];
                    #pragma unroll
                    for (int p = 0; p < 3; p++) curB[p] = nxtB[p];
                }
            }
        }

        // ---- rare fix-up (warp-uniformly skipped ~always): fp32 global gathers ----
        if (__any_sync(0xffffffffu, fixup)) {
            if (fixup) {
                r0 = 0.0f; r1 = 0.0f; r2 = 0.0f;
                #pragma unroll 1
                for (int r = 0; r < 5; r++) {
                    const int yy = min(max(iy - 1 + r, 0), H_ - 1);
                    const float* g0 = ibase + yy * W_;
                    #pragma unroll 1
                    for (int c = 0; c < 5; c++) {
                        float w = 0.0f;
                        if (r < 4 && c < 4)  w += wTL * f[r * 4 + c];
                        if (r < 4 && c >= 1) w += wTR * f[r * 4 + c - 1];
                        if (r >= 1 && c < 4) w += wBL * f[(r - 1) * 4 + c];
                        if (r >= 1 && c >= 1)w += wBR * f[(r - 1) * 4 + c - 1];

                        const int xo = min(max(ix - 1 + c, 0), W_ - 1);
                        r0 += w * __ldg(g0 + xo);
                        r1 += w * __ldg(g0 + xo + HW_);
                        r2 += w * __ldg(g0 + xo + 2 * HW_);
                    }
                }
            }
        }

        float* ob = obb + pix;
        __stcs(ob,            r0 * validf);
        __stcs(ob + HW_,      r1 * validf);
        __stcs(ob + 2 * HW_,  r2 * validf);
    }
}

extern "C" void kernel_launch(void* const* d_in, const int* in_sizes, int n_in,
                              void* d_out, int out_size)
{
    const float* teninput  = (const float*)d_in[0];
    const float* tenflow   = (const float*)d_in[1];
    const float* tenfilter = (const float*)d_in[2];
    float* out = (float*)d_out;

    dim3 grid(W_ / TW, H_ / TH, B_);   // 15 x 32 x 4
    fi_tiled_h14_kernel<<<grid, NTHREADS>>>(teninput, tenflow, tenfilter, out);
}